// round 3
// baseline (speedup 1.0000x reference)
#include <cuda_runtime.h>

#define NB    4096
#define NPOSE 13
#define NHID  256
#define NG3   768
#define NIN   269
#define NCTX  256
#define BT    28      // batch rows per CTA
#define NPR   14      // row pairs per CTA
#define NQ4   7       // float4 groups per 28-row strip
#define NTHR  256

// k-major (transposed) weight scratch, built by prep_kernel each launch.
__device__ float g_Wpt [NPOSE * NHID];            // W_in pose part: [k][j]
__device__ float g_Wct [NCTX  * NHID];            // W_in ctx part:  [k][j]
// Fused gate weights, k-paired: [k2][gate 0..5][j] -> float2 {w(2k2), w(2k2+1)}
// gates: 0=i_r 1=i_z 2=i_n 3=h_r 4=h_z 5=h_n
__device__ float g_Wg2 [(NHID / 2) * 6 * NHID * 2];

// Packed dual-fp32 FMA (Blackwell f32x2 pipe; ptxas never auto-fuses this).
__device__ __forceinline__ float2 ffma2(float2 a, float2 b, float2 c) {
    float2 d;
    asm("fma.rn.f32x2 %0, %1, %2, %3;"
        : "=l"(*reinterpret_cast<unsigned long long*>(&d))
        : "l"(*reinterpret_cast<unsigned long long*>(&a)),
          "l"(*reinterpret_cast<unsigned long long*>(&b)),
          "l"(*reinterpret_cast<unsigned long long*>(&c)));
    return d;
}

__device__ __forceinline__ float sigm(float a) {
    return 1.0f / (1.0f + __expf(-a));
}
__device__ __forceinline__ float tanh_acc(float a) {
    float e = __expf(-2.0f * fabsf(a));      // e in (0,1], overflow-safe
    float t = (1.0f - e) / (1.0f + e);
    return copysignf(t, a);
}

__global__ void prep_kernel(const float* __restrict__ W_in,
                            const float* __restrict__ W_ih,
                            const float* __restrict__ W_hh) {
    int i = blockIdx.x * blockDim.x + threadIdx.x;
    if (i < NPOSE * NHID) {
        int k = i / NHID, j = i % NHID;
        g_Wpt[i] = W_in[j * NIN + k];
    }
    if (i < NCTX * NHID) {
        int k = i / NHID, j = i % NHID;
        g_Wct[i] = W_in[j * NIN + NPOSE + k];
    }
    // g_Wg2: (NHID/2)*6*NHID float2 entries = 196608 = NHID*NG3 threads' worth
    if (i < (NHID / 2) * 6 * NHID) {
        int k2  = i / (6 * NHID);
        int rem = i % (6 * NHID);
        int g   = rem / NHID;
        int j   = rem % NHID;
        int k0  = 2 * k2, k1 = 2 * k2 + 1;
        float a, b;
        if (g < 3) {
            const float* row = W_ih + (size_t)(g * NHID + j) * NHID;
            a = row[k0]; b = row[k1];
        } else {
            const float* row = W_hh + (size_t)((g - 3) * NHID + j) * NHID;
            a = row[k0]; b = row[k1];
        }
        reinterpret_cast<float2*>(g_Wg2)[i] = make_float2(a, b);
    }
}

__global__ __launch_bounds__(NTHR, 1)
void rnn_kernel(const float* __restrict__ last_pose,
                const float* __restrict__ context,
                const int*   __restrict__ d_nf,
                const float* __restrict__ b_in,
                const float* __restrict__ b_ih,
                const float* __restrict__ b_hh,
                const float* __restrict__ W_out,
                const float* __restrict__ b_out,
                float*       __restrict__ out)
{
    extern __shared__ float sm[];
    float* s_ctx  = sm;                     // [256][28]  ctx, row-minor
    float* s_x    = s_ctx  + NCTX * BT;     // [256][28]  x,   row-minor
    float* s_h0   = s_x    + NHID * BT;     // [256][28]  h ping
    float* s_h1   = s_h0   + NHID * BT;     // [256][28]  h pong
    float* s_pose = s_h1   + NHID * BT;     // [16][28]   pose (13 used)
    float* s_raw  = s_pose + 16 * BT;       // [16][28]   pre-norm pose

    const int j    = threadIdx.x;           // hidden unit owned by this thread
    const int row0 = blockIdx.x * BT;
    const int nf   = d_nf[0];

    // --- init: ctx transposed load, h=0, pose transposed load ---
    #pragma unroll 4
    for (int r = 0; r < BT; r++) {
        int grow = row0 + r; if (grow > NB - 1) grow = NB - 1;   // clamp pad rows
        s_ctx[j * BT + r] = context[(size_t)grow * NCTX + j];
        s_h0 [j * BT + r] = 0.0f;
    }
    if (j < NPOSE) {
        for (int r = 0; r < BT; r++) {
            int grow = row0 + r; if (grow > NB - 1) grow = NB - 1;
            s_pose[j * BT + r] = last_pose[(size_t)grow * NPOSE + j];
        }
    }
    const float binj = b_in[j];
    const float brz0 = b_ih[j]        + b_hh[j];          // fused r bias
    const float brz1 = b_ih[NHID + j] + b_hh[NHID + j];   // fused z bias
    const float bin_ = b_ih[2 * NHID + j];
    const float bhn  = b_hh[2 * NHID + j];
    __syncthreads();

    for (int t = 0; t < nf; t++) {
        const float* hprev = (t & 1) ? s_h1 : s_h0;
        float*       hnext = (t & 1) ? s_h0 : s_h1;

        // ---- Phase A: x = relu(W_in @ [pose; ctx] + b_in), unit j, 28 rows ----
        float2 ax[NPR];
        #pragma unroll
        for (int p = 0; p < NPR; p++) ax[p] = make_float2(binj, binj);

        #pragma unroll
        for (int k = 0; k < NPOSE; k++) {
            float w = g_Wpt[k * NHID + j];
            float2 w2 = make_float2(w, w);
            const float4* pr = reinterpret_cast<const float4*>(s_pose + k * BT);
            #pragma unroll
            for (int q = 0; q < NQ4; q++) {
                float4 v = pr[q];
                ax[2*q]   = ffma2(make_float2(v.x, v.y), w2, ax[2*q]);
                ax[2*q+1] = ffma2(make_float2(v.z, v.w), w2, ax[2*q+1]);
            }
        }
        #pragma unroll 4
        for (int k = 0; k < NCTX; k++) {
            float w = g_Wct[k * NHID + j];
            float2 w2 = make_float2(w, w);
            const float4* cr = reinterpret_cast<const float4*>(s_ctx + k * BT);
            #pragma unroll
            for (int q = 0; q < NQ4; q++) {
                float4 v = cr[q];
                ax[2*q]   = ffma2(make_float2(v.x, v.y), w2, ax[2*q]);
                ax[2*q+1] = ffma2(make_float2(v.z, v.w), w2, ax[2*q+1]);
            }
        }
        {
            float2* xo = reinterpret_cast<float2*>(s_x + j * BT);
            #pragma unroll
            for (int p = 0; p < NPR; p++)
                xo[p] = make_float2(fmaxf(ax[p].x, 0.0f), fmaxf(ax[p].y, 0.0f));
        }
        __syncthreads();

        // ---- Phase B: gate GEMM columns for unit j, 28 rows, f32x2 packed ----
        // r/z accumulators FUSED (i_r+h_r, i_z+h_z); n keeps i_n, h_n separate
        // (needed for r * h_n). 112 accumulator regs -> no spills.
        float2 ar[NPR], az[NPR], ani[NPR], anh[NPR];
        #pragma unroll
        for (int p = 0; p < NPR; p++) {
            ar[p] = make_float2(0.f, 0.f);
            az[p] = ar[p]; ani[p] = ar[p]; anh[p] = ar[p];
        }
        for (int k2 = 0; k2 < NHID / 2; k2++) {
            // one float2 per gate covers k = 2*k2 and 2*k2+1 (lane-coalesced)
            const float2* wg = reinterpret_cast<const float2*>(g_Wg2)
                             + (size_t)k2 * 6 * NHID + j;
            float2 wir = wg[0];
            float2 wiz = wg[NHID];
            float2 win = wg[2 * NHID];
            float2 whr = wg[3 * NHID];
            float2 whz = wg[4 * NHID];
            float2 whn = wg[5 * NHID];
            #pragma unroll
            for (int s = 0; s < 2; s++) {
                int k = 2 * k2 + s;
                float2 wir2 = make_float2(s ? wir.y : wir.x, s ? wir.y : wir.x);
                float2 wiz2 = make_float2(s ? wiz.y : wiz.x, s ? wiz.y : wiz.x);
                float2 win2 = make_float2(s ? win.y : win.x, s ? win.y : win.x);
                float2 whr2 = make_float2(s ? whr.y : whr.x, s ? whr.y : whr.x);
                float2 whz2 = make_float2(s ? whz.y : whz.x, s ? whz.y : whz.x);
                float2 whn2 = make_float2(s ? whn.y : whn.x, s ? whn.y : whn.x);
                const float4* xr = reinterpret_cast<const float4*>(s_x   + k * BT);
                const float4* hr = reinterpret_cast<const float4*>(hprev + k * BT);
                #pragma unroll
                for (int q = 0; q < NQ4; q++) {
                    float4 xv = xr[q];             // LDS.128 broadcast
                    float4 hv = hr[q];
                    float2 x0 = make_float2(xv.x, xv.y), x1 = make_float2(xv.z, xv.w);
                    float2 h0 = make_float2(hv.x, hv.y), h1 = make_float2(hv.z, hv.w);
                    ar [2*q]   = ffma2(x0, wir2, ar [2*q]);
                    ar [2*q]   = ffma2(h0, whr2, ar [2*q]);
                    ar [2*q+1] = ffma2(x1, wir2, ar [2*q+1]);
                    ar [2*q+1] = ffma2(h1, whr2, ar [2*q+1]);
                    az [2*q]   = ffma2(x0, wiz2, az [2*q]);
                    az [2*q]   = ffma2(h0, whz2, az [2*q]);
                    az [2*q+1] = ffma2(x1, wiz2, az [2*q+1]);
                    az [2*q+1] = ffma2(h1, whz2, az [2*q+1]);
                    ani[2*q]   = ffma2(x0, win2, ani[2*q]);
                    ani[2*q+1] = ffma2(x1, win2, ani[2*q+1]);
                    anh[2*q]   = ffma2(h0, whn2, anh[2*q]);
                    anh[2*q+1] = ffma2(h1, whn2, anh[2*q+1]);
                }
            }
        }

        // ---- Phase C: GRU gates + h_new (registers only for unit j) ----
        {
            const float2* hop = reinterpret_cast<const float2*>(hprev + j * BT);
            float2*       hnp = reinterpret_cast<float2*>(hnext + j * BT);
            #pragma unroll
            for (int p = 0; p < NPR; p++) {
                float2 ho = hop[p];
                float rr = sigm(ar[p].x + brz0);
                float zz = sigm(az[p].x + brz1);
                float nn = tanh_acc(ani[p].x + bin_ + rr * (anh[p].x + bhn));
                float hx = (1.0f - zz) * nn + zz * ho.x;
                rr = sigm(ar[p].y + brz0);
                zz = sigm(az[p].y + brz1);
                nn = tanh_acc(ani[p].y + bin_ + rr * (anh[p].y + bhn));
                float hy = (1.0f - zz) * nn + zz * ho.y;
                hnp[p] = make_float2(hx, hy);
            }
        }
        __syncthreads();

        // ---- Phase D1: pose delta = h_new @ W_out^T + b_out ----
        for (int u = j; u < NPOSE * BT; u += NTHR) {
            int p = u / BT, r = u - p * BT;
            const float4* wo = reinterpret_cast<const float4*>(W_out + p * NHID);
            float acc = b_out[p];
            #pragma unroll 4
            for (int k4 = 0; k4 < NHID / 4; k4++) {
                float4 w4 = wo[k4];
                int kb = k4 * 4;
                acc = fmaf(hnext[(kb    ) * BT + r], w4.x, acc);
                acc = fmaf(hnext[(kb + 1) * BT + r], w4.y, acc);
                acc = fmaf(hnext[(kb + 2) * BT + r], w4.z, acc);
                acc = fmaf(hnext[(kb + 3) * BT + r], w4.w, acc);
            }
            s_raw[u] = s_pose[u] + acc;
        }
        __syncthreads();

        // ---- Phase D2: quaternion normalize + commit pose + store output ----
        for (int u = j; u < NPOSE * BT; u += NTHR) {
            int p = u / BT, r = u - p * BT;
            float v = s_raw[u];
            if (p >= 3 && p <= 6) {
                float q3 = s_raw[3 * BT + r], q4 = s_raw[4 * BT + r];
                float q5 = s_raw[5 * BT + r], q6 = s_raw[6 * BT + r];
                float nrm = fmaxf(sqrtf(q3*q3 + q4*q4 + q5*q5 + q6*q6), 1e-12f);
                v = v / nrm;
            }
            s_pose[u] = v;
            int grow = row0 + r;
            if (grow < NB)
                out[((size_t)grow * nf + t) * NPOSE + p] = v;
        }
        __syncthreads();
    }
}

extern "C" void kernel_launch(void* const* d_in, const int* in_sizes, int n_in,
                              void* d_out, int out_size) {
    const float* last_pose = (const float*)d_in[0];
    const float* context   = (const float*)d_in[1];
    const int*   num_fut   = (const int*)  d_in[2];
    const float* W_in      = (const float*)d_in[3];
    const float* b_in      = (const float*)d_in[4];
    const float* W_ih      = (const float*)d_in[5];
    const float* b_ih      = (const float*)d_in[6];
    const float* W_hh      = (const float*)d_in[7];
    const float* b_hh      = (const float*)d_in[8];
    const float* W_out     = (const float*)d_in[9];
    const float* b_out     = (const float*)d_in[10];
    float* out = (float*)d_out;

    // k-major weight transposes (cheap, L2-resident, deterministic each call)
    prep_kernel<<<((NHID / 2) * 6 * NHID + 255) / 256, 256>>>(W_in, W_ih, W_hh);

    const int smem_bytes = (NCTX * BT + 3 * NHID * BT + 2 * 16 * BT) * (int)sizeof(float);
    cudaFuncSetAttribute(rnn_kernel,
                         cudaFuncAttributeMaxDynamicSharedMemorySize, smem_bytes);

    const int grid = (NB + BT - 1) / BT;   // 147 CTAs -> one wave
    rnn_kernel<<<grid, NTHR, smem_bytes>>>(last_pose, context, num_fut,
                                           b_in, b_ih, b_hh, W_out, b_out, out);
}

// round 4
// speedup vs baseline: 1.2885x; 1.2885x over previous
#include <cuda_runtime.h>

#define NB    4096
#define NPOSE 13
#define NHID  256
#define NIN   269
#define NCTX  256
#define BT    28      // batch rows per CTA
#define NTHR  512     // two warpgroups: half 0 -> rows 0..15, half 1 -> rows 16..27

// Duplicated-pair weights, built by prep_kernel each launch (deterministic).
__device__ float2 g_Wptd[NPOSE * NHID];          // W_in pose part: [k][j] -> (w,w)
__device__ float2 g_Wctd[NCTX  * NHID];          // W_in ctx  part: [k][j] -> (w,w)
// gates: 0=i_r 1=i_z 2=i_n 3=h_r 4=h_z 5=h_n ;  [k][gate][j] -> (w,w)
__device__ float2 g_Wgd [NHID * 6 * NHID];

// Packed dual-fp32 FMA (Blackwell f32x2 pipe; only reachable via PTX).
__device__ __forceinline__ float2 ffma2(float2 a, float2 b, float2 c) {
    float2 d;
    asm("fma.rn.f32x2 %0, %1, %2, %3;"
        : "=l"(*reinterpret_cast<unsigned long long*>(&d))
        : "l"(*reinterpret_cast<unsigned long long*>(&a)),
          "l"(*reinterpret_cast<unsigned long long*>(&b)),
          "l"(*reinterpret_cast<unsigned long long*>(&c)));
    return d;
}

__device__ __forceinline__ float sigm(float a) {
    return 1.0f / (1.0f + __expf(-a));
}
__device__ __forceinline__ float tanh_acc(float a) {
    float e = __expf(-2.0f * fabsf(a));      // e in (0,1], overflow-safe
    float t = (1.0f - e) / (1.0f + e);
    return copysignf(t, a);
}

__global__ void prep_kernel(const float* __restrict__ W_in,
                            const float* __restrict__ W_ih,
                            const float* __restrict__ W_hh) {
    int i = blockIdx.x * blockDim.x + threadIdx.x;
    if (i < NPOSE * NHID) {
        int k = i / NHID, j = i % NHID;
        float w = W_in[j * NIN + k];
        g_Wptd[i] = make_float2(w, w);
    }
    if (i < NCTX * NHID) {
        int k = i / NHID, j = i % NHID;
        float w = W_in[j * NIN + NPOSE + k];
        g_Wctd[i] = make_float2(w, w);
    }
    if (i < NHID * 6 * NHID) {
        int k   = i / (6 * NHID);
        int rem = i % (6 * NHID);
        int g   = rem / NHID;
        int j   = rem % NHID;
        float w = (g < 3) ? W_ih[(size_t)(g * NHID + j) * NHID + k]
                          : W_hh[(size_t)((g - 3) * NHID + j) * NHID + k];
        g_Wgd[i] = make_float2(w, w);
    }
}

// Dense input GEMM column for unit j over this half's rows:
// ax[2q],ax[2q+1] accumulate src[k][rows] * Wd[k][j] (Wd pre-duplicated).
template<int NQH, int QOFF>
__device__ __forceinline__ void gemm_in(const float2* __restrict__ Wd, int nk,
                                        const float* __restrict__ src, int j,
                                        float2* ax)
{
    #pragma unroll 4
    for (int k = 0; k < nk; k++) {
        float2 w2 = Wd[k * NHID + j];
        const float4* pr = reinterpret_cast<const float4*>(src + k * BT) + QOFF;
        #pragma unroll
        for (int q = 0; q < NQH; q++) {
            float4 v = pr[q];
            ax[2*q]   = ffma2(make_float2(v.x, v.y), w2, ax[2*q]);
            ax[2*q+1] = ffma2(make_float2(v.z, v.w), w2, ax[2*q+1]);
        }
    }
}

// Phase B (six gate GEMM columns) + Phase C (GRU pointwise), unit j, this half's rows.
template<int NQH, int QOFF>
__device__ __forceinline__ void gru_step(const float* __restrict__ s_x,
                                         const float* __restrict__ hprev,
                                         float*       __restrict__ hnext,
                                         int j,
                                         float brz0, float brz1,
                                         float bin_, float bhn)
{
    constexpr int NP = 2 * NQH;
    float2 ar[NP], az[NP], ani[NP], anh[NP];
    #pragma unroll
    for (int p = 0; p < NP; p++) {
        ar[p] = make_float2(0.f, 0.f);
        az[p] = ar[p]; ani[p] = ar[p]; anh[p] = ar[p];
    }
    #pragma unroll 2
    for (int k = 0; k < NHID; k++) {
        const float2* wg = g_Wgd + (size_t)k * (6 * NHID) + j;   // lane-coalesced LDG.64
        float2 wir = wg[0];
        float2 wiz = wg[NHID];
        float2 win = wg[2 * NHID];
        float2 whr = wg[3 * NHID];
        float2 whz = wg[4 * NHID];
        float2 whn = wg[5 * NHID];
        const float4* xr = reinterpret_cast<const float4*>(s_x   + k * BT) + QOFF;
        const float4* hr = reinterpret_cast<const float4*>(hprev + k * BT) + QOFF;
        #pragma unroll
        for (int q = 0; q < NQH; q++) {
            float4 xv = xr[q];                 // LDS.128 broadcast (conflict-free)
            float4 hv = hr[q];
            float2 x0 = make_float2(xv.x, xv.y), x1 = make_float2(xv.z, xv.w);
            float2 h0 = make_float2(hv.x, hv.y), h1 = make_float2(hv.z, hv.w);
            ar [2*q]   = ffma2(x0, wir, ar [2*q]);
            ar [2*q]   = ffma2(h0, whr, ar [2*q]);
            ar [2*q+1] = ffma2(x1, wir, ar [2*q+1]);
            ar [2*q+1] = ffma2(h1, whr, ar [2*q+1]);
            az [2*q]   = ffma2(x0, wiz, az [2*q]);
            az [2*q]   = ffma2(h0, whz, az [2*q]);
            az [2*q+1] = ffma2(x1, wiz, az [2*q+1]);
            az [2*q+1] = ffma2(h1, whz, az [2*q+1]);
            ani[2*q]   = ffma2(x0, win, ani[2*q]);
            ani[2*q+1] = ffma2(x1, win, ani[2*q+1]);
            anh[2*q]   = ffma2(h0, whn, anh[2*q]);
            anh[2*q+1] = ffma2(h1, whn, anh[2*q+1]);
        }
    }
    // GRU pointwise, registers only
    const float2* hop = reinterpret_cast<const float2*>(hprev + j * BT) + QOFF * 2;
    float2*       hnp = reinterpret_cast<float2*>(hnext + j * BT) + QOFF * 2;
    #pragma unroll
    for (int p = 0; p < NP; p++) {
        float2 ho = hop[p];
        float rr = sigm(ar[p].x + brz0);
        float zz = sigm(az[p].x + brz1);
        float nn = tanh_acc(ani[p].x + bin_ + rr * (anh[p].x + bhn));
        float hx = (1.0f - zz) * nn + zz * ho.x;
        rr = sigm(ar[p].y + brz0);
        zz = sigm(az[p].y + brz1);
        nn = tanh_acc(ani[p].y + bin_ + rr * (anh[p].y + bhn));
        float hy = (1.0f - zz) * nn + zz * ho.y;
        hnp[p] = make_float2(hx, hy);
    }
}

__global__ __launch_bounds__(NTHR, 1)
void rnn_kernel(const float* __restrict__ last_pose,
                const float* __restrict__ context,
                const int*   __restrict__ d_nf,
                const float* __restrict__ b_in,
                const float* __restrict__ b_ih,
                const float* __restrict__ b_hh,
                const float* __restrict__ W_out,
                const float* __restrict__ b_out,
                float*       __restrict__ out)
{
    extern __shared__ float sm[];
    float* s_cb   = sm;                     // [256][28]  c_base = Wc@ctx + b_in
    float* s_x    = s_cb  + NHID * BT;      // [256][28]  x (temp: raw ctx at init)
    float* s_h0   = s_x   + NHID * BT;      // [256][28]  h ping
    float* s_h1   = s_h0  + NHID * BT;      // [256][28]  h pong
    float* s_pose = s_h1  + NHID * BT;      // [16][28]   pose (13 used)
    float* s_raw  = s_pose + 16 * BT;       // [16][28]   pre-norm pose

    const int tid  = threadIdx.x;
    const int j    = tid & (NHID - 1);      // hidden unit owned by this thread
    const int half = tid >> 8;              // 0: rows 0..15 (4 q), 1: rows 16..27 (3 q)
    const int r0   = half * 16;
    const int nr   = half ? 12 : 16;
    const int row0 = blockIdx.x * BT;
    const int nf   = d_nf[0];

    // --- init: raw ctx -> s_x (transposed), h=0; pose -> s_pose ---
    for (int rr = 0; rr < nr; rr++) {
        int r = r0 + rr;
        int grow = row0 + r; if (grow > NB - 1) grow = NB - 1;   // clamp pad rows
        s_x [j * BT + r] = context[(size_t)grow * NCTX + j];
        s_h0[j * BT + r] = 0.0f;
    }
    if (tid < NPOSE * BT) {
        int p = tid / BT, r = tid - p * BT;
        int grow = row0 + r; if (grow > NB - 1) grow = NB - 1;
        s_pose[p * BT + r] = last_pose[(size_t)grow * NPOSE + p];
    }
    const float binj = b_in[j];
    const float brz0 = b_ih[j]        + b_hh[j];          // fused r bias
    const float brz1 = b_ih[NHID + j] + b_hh[NHID + j];   // fused z bias
    const float bin_ = b_ih[2 * NHID + j];
    const float bhn  = b_hh[2 * NHID + j];
    __syncthreads();

    // --- precompute c_base = Wc @ ctx + b_in (hoisted out of the time loop) ---
    {
        float2 cb[8];
        if (half == 0) {
            #pragma unroll
            for (int p = 0; p < 8; p++) cb[p] = make_float2(binj, binj);
            gemm_in<4, 0>(g_Wctd, NCTX, s_x, j, cb);
            float2* co = reinterpret_cast<float2*>(s_cb + j * BT);
            #pragma unroll
            for (int p = 0; p < 8; p++) co[p] = cb[p];
        } else {
            #pragma unroll
            for (int p = 0; p < 6; p++) cb[p] = make_float2(binj, binj);
            gemm_in<3, 4>(g_Wctd, NCTX, s_x, j, cb);
            float2* co = reinterpret_cast<float2*>(s_cb + j * BT) + 8;
            #pragma unroll
            for (int p = 0; p < 6; p++) co[p] = cb[p];
        }
    }
    __syncthreads();

    for (int t = 0; t < nf; t++) {
        const float* hprev = (t & 1) ? s_h1 : s_h0;
        float*       hnext = (t & 1) ? s_h0 : s_h1;

        // ---- Phase A: x = relu(c_base + Wp @ pose), only 13 k-iterations ----
        if (half == 0) {
            float2 ax[8];
            const float2* cb = reinterpret_cast<const float2*>(s_cb + j * BT);
            #pragma unroll
            for (int p = 0; p < 8; p++) ax[p] = cb[p];
            gemm_in<4, 0>(g_Wptd, NPOSE, s_pose, j, ax);
            float2* xo = reinterpret_cast<float2*>(s_x + j * BT);
            #pragma unroll
            for (int p = 0; p < 8; p++)
                xo[p] = make_float2(fmaxf(ax[p].x, 0.0f), fmaxf(ax[p].y, 0.0f));
        } else {
            float2 ax[6];
            const float2* cb = reinterpret_cast<const float2*>(s_cb + j * BT) + 8;
            #pragma unroll
            for (int p = 0; p < 6; p++) ax[p] = cb[p];
            gemm_in<3, 4>(g_Wptd, NPOSE, s_pose, j, ax);
            float2* xo = reinterpret_cast<float2*>(s_x + j * BT) + 8;
            #pragma unroll
            for (int p = 0; p < 6; p++)
                xo[p] = make_float2(fmaxf(ax[p].x, 0.0f), fmaxf(ax[p].y, 0.0f));
        }
        __syncthreads();

        // ---- Phase B + C: gate GEMMs + GRU pointwise ----
        if (half == 0) gru_step<4, 0>(s_x, hprev, hnext, j, brz0, brz1, bin_, bhn);
        else           gru_step<3, 4>(s_x, hprev, hnext, j, brz0, brz1, bin_, bhn);
        __syncthreads();

        // ---- Phase D1: pose delta = h_new @ W_out^T + b_out (364 units) ----
        if (tid < NPOSE * BT) {
            int p = tid / BT, r = tid - p * BT;
            const float4* wo = reinterpret_cast<const float4*>(W_out + p * NHID);
            float acc = b_out[p];
            #pragma unroll 4
            for (int k4 = 0; k4 < NHID / 4; k4++) {
                float4 w4 = wo[k4];
                int kb = k4 * 4;
                acc = fmaf(hnext[(kb    ) * BT + r], w4.x, acc);
                acc = fmaf(hnext[(kb + 1) * BT + r], w4.y, acc);
                acc = fmaf(hnext[(kb + 2) * BT + r], w4.z, acc);
                acc = fmaf(hnext[(kb + 3) * BT + r], w4.w, acc);
            }
            s_raw[tid] = s_pose[tid] + acc;
        }
        __syncthreads();

        // ---- Phase D2: quaternion normalize + commit pose + store output ----
        if (tid < NPOSE * BT) {
            int p = tid / BT, r = tid - p * BT;
            float v = s_raw[tid];
            if (p >= 3 && p <= 6) {
                float q3 = s_raw[3 * BT + r], q4 = s_raw[4 * BT + r];
                float q5 = s_raw[5 * BT + r], q6 = s_raw[6 * BT + r];
                float nrm = fmaxf(sqrtf(q3*q3 + q4*q4 + q5*q5 + q6*q6), 1e-12f);
                v = v / nrm;
            }
            s_pose[tid] = v;
            int grow = row0 + r;
            if (grow < NB)
                out[((size_t)grow * nf + t) * NPOSE + p] = v;
        }
        __syncthreads();
    }
}

extern "C" void kernel_launch(void* const* d_in, const int* in_sizes, int n_in,
                              void* d_out, int out_size) {
    const float* last_pose = (const float*)d_in[0];
    const float* context   = (const float*)d_in[1];
    const int*   num_fut   = (const int*)  d_in[2];
    const float* W_in      = (const float*)d_in[3];
    const float* b_in      = (const float*)d_in[4];
    const float* W_ih      = (const float*)d_in[5];
    const float* b_ih      = (const float*)d_in[6];
    const float* W_hh      = (const float*)d_in[7];
    const float* b_hh      = (const float*)d_in[8];
    const float* W_out     = (const float*)d_in[9];
    const float* b_out     = (const float*)d_in[10];
    float* out = (float*)d_out;

    // duplicated-pair weight transposes (L2-resident, deterministic each call)
    prep_kernel<<<(NHID * 6 * NHID + 255) / 256, 256>>>(W_in, W_ih, W_hh);

    const int smem_bytes = (4 * NHID * BT + 2 * 16 * BT) * (int)sizeof(float);
    cudaFuncSetAttribute(rnn_kernel,
                         cudaFuncAttributeMaxDynamicSharedMemorySize, smem_bytes);

    const int grid = (NB + BT - 1) / BT;   // 147 CTAs -> one wave
    rnn_kernel<<<grid, NTHR, smem_bytes>>>(last_pose, context, num_fut,
                                           b_in, b_ih, b_hh, W_out, b_out, out);
}

// round 5
// speedup vs baseline: 1.4960x; 1.1610x over previous
#include <cuda_runtime.h>

#define NB    4096
#define NPOSE 13
#define NHID  256
#define NIN   269
#define NCTX  256
#define BT    28      // batch rows per CTA
#define NTHR  512     // two halves: half 0 -> rows 0..15, half 1 -> rows 16..27

// Input-layer weights stay duplicated (tiny: 13 + one-time-256 k iterations).
__device__ float2 g_Wptd[NPOSE * NHID];          // W_in pose part: [k][j] -> (w,w)
__device__ float2 g_Wctd[NCTX  * NHID];          // W_in ctx  part: [k][j] -> (w,w)
// Gate weights PACKED, non-duplicated: 2 LDGs per k per thread.
__device__ float4 g_W4[NHID * NHID];             // [k][j] -> (w_ir, w_iz, w_in, w_hr)
__device__ float2 g_W2[NHID * NHID];             // [k][j] -> (w_hz, w_hn)

// Packed dual-fp32 FMA (Blackwell f32x2 pipe; only reachable via PTX).
__device__ __forceinline__ float2 ffma2(float2 a, float2 b, float2 c) {
    float2 d;
    asm("fma.rn.f32x2 %0, %1, %2, %3;"
        : "=l"(*reinterpret_cast<unsigned long long*>(&d))
        : "l"(*reinterpret_cast<unsigned long long*>(&a)),
          "l"(*reinterpret_cast<unsigned long long*>(&b)),
          "l"(*reinterpret_cast<unsigned long long*>(&c)));
    return d;
}

__device__ __forceinline__ float sigm(float a) {
    return 1.0f / (1.0f + __expf(-a));
}
__device__ __forceinline__ float tanh_acc(float a) {
    float e = __expf(-2.0f * fabsf(a));      // e in (0,1], overflow-safe
    float t = (1.0f - e) / (1.0f + e);
    return copysignf(t, a);
}

__global__ void prep_kernel(const float* __restrict__ W_in,
                            const float* __restrict__ W_ih,
                            const float* __restrict__ W_hh) {
    int i = blockIdx.x * blockDim.x + threadIdx.x;
    if (i < NPOSE * NHID) {
        int k = i / NHID, j = i % NHID;
        float w = W_in[j * NIN + k];
        g_Wptd[i] = make_float2(w, w);
    }
    if (i < NCTX * NHID) {
        int k = i / NHID, j = i % NHID;
        float w = W_in[j * NIN + NPOSE + k];
        g_Wctd[i] = make_float2(w, w);
    }
    if (i < NHID * NHID) {
        int k = i / NHID, j = i % NHID;
        g_W4[i] = make_float4(W_ih[(size_t)(0 * NHID + j) * NHID + k],
                              W_ih[(size_t)(1 * NHID + j) * NHID + k],
                              W_ih[(size_t)(2 * NHID + j) * NHID + k],
                              W_hh[(size_t)(0 * NHID + j) * NHID + k]);
        g_W2[i] = make_float2(W_hh[(size_t)(1 * NHID + j) * NHID + k],
                              W_hh[(size_t)(2 * NHID + j) * NHID + k]);
    }
}

// Dense input GEMM column for unit j over this half's rows (duplicated weights).
template<int NQH, int QOFF>
__device__ __forceinline__ void gemm_in(const float2* __restrict__ Wd, int nk,
                                        const float* __restrict__ src, int j,
                                        float2* ax)
{
    #pragma unroll 4
    for (int k = 0; k < nk; k++) {
        float2 w2 = Wd[k * NHID + j];
        const float4* pr = reinterpret_cast<const float4*>(src + k * BT) + QOFF;
        #pragma unroll
        for (int q = 0; q < NQH; q++) {
            float4 v = pr[q];
            ax[2*q]   = ffma2(make_float2(v.x, v.y), w2, ax[2*q]);
            ax[2*q+1] = ffma2(make_float2(v.z, v.w), w2, ax[2*q+1]);
        }
    }
}

// Phase B (six gate GEMM columns) + Phase C (GRU pointwise), unit j, this half's rows.
template<int NQH, int QOFF>
__device__ __forceinline__ void gru_step(const float* __restrict__ s_x,
                                         const float* __restrict__ hprev,
                                         float*       __restrict__ hnext,
                                         int j,
                                         float brz0, float brz1,
                                         float bin_, float bhn)
{
    constexpr int NP = 2 * NQH;
    float2 ar[NP], az[NP], ani[NP], anh[NP];
    #pragma unroll
    for (int p = 0; p < NP; p++) {
        ar[p] = make_float2(0.f, 0.f);
        az[p] = ar[p]; ani[p] = ar[p]; anh[p] = ar[p];
    }
    #pragma unroll 2
    for (int k = 0; k < NHID; k++) {
        // 2 packed LDGs (128b + 64b), lane-coalesced; dup to lane-pairs via
        // alu-pipe MOVs (fma pipe untouched).
        float4 wa = g_W4[k * NHID + j];
        float2 wb = g_W2[k * NHID + j];
        float2 wir = make_float2(wa.x, wa.x);
        float2 wiz = make_float2(wa.y, wa.y);
        float2 win = make_float2(wa.z, wa.z);
        float2 whr = make_float2(wa.w, wa.w);
        float2 whz = make_float2(wb.x, wb.x);
        float2 whn = make_float2(wb.y, wb.y);
        const float4* xr = reinterpret_cast<const float4*>(s_x   + k * BT) + QOFF;
        const float4* hr = reinterpret_cast<const float4*>(hprev + k * BT) + QOFF;
        #pragma unroll
        for (int q = 0; q < NQH; q++) {
            float4 xv = xr[q];                 // LDS.128 broadcast (conflict-free)
            float4 hv = hr[q];
            float2 x0 = make_float2(xv.x, xv.y), x1 = make_float2(xv.z, xv.w);
            float2 h0 = make_float2(hv.x, hv.y), h1 = make_float2(hv.z, hv.w);
            ar [2*q]   = ffma2(x0, wir, ar [2*q]);
            ar [2*q]   = ffma2(h0, whr, ar [2*q]);
            ar [2*q+1] = ffma2(x1, wir, ar [2*q+1]);
            ar [2*q+1] = ffma2(h1, whr, ar [2*q+1]);
            az [2*q]   = ffma2(x0, wiz, az [2*q]);
            az [2*q]   = ffma2(h0, whz, az [2*q]);
            az [2*q+1] = ffma2(x1, wiz, az [2*q+1]);
            az [2*q+1] = ffma2(h1, whz, az [2*q+1]);
            ani[2*q]   = ffma2(x0, win, ani[2*q]);
            ani[2*q+1] = ffma2(x1, win, ani[2*q+1]);
            anh[2*q]   = ffma2(h0, whn, anh[2*q]);
            anh[2*q+1] = ffma2(h1, whn, anh[2*q+1]);
        }
    }
    // GRU pointwise, registers only
    const float2* hop = reinterpret_cast<const float2*>(hprev + j * BT) + QOFF * 2;
    float2*       hnp = reinterpret_cast<float2*>(hnext + j * BT) + QOFF * 2;
    #pragma unroll
    for (int p = 0; p < NP; p++) {
        float2 ho = hop[p];
        float rr = sigm(ar[p].x + brz0);
        float zz = sigm(az[p].x + brz1);
        float nn = tanh_acc(ani[p].x + bin_ + rr * (anh[p].x + bhn));
        float hx = (1.0f - zz) * nn + zz * ho.x;
        rr = sigm(ar[p].y + brz0);
        zz = sigm(az[p].y + brz1);
        nn = tanh_acc(ani[p].y + bin_ + rr * (anh[p].y + bhn));
        float hy = (1.0f - zz) * nn + zz * ho.y;
        hnp[p] = make_float2(hx, hy);
    }
}

__global__ __launch_bounds__(NTHR, 1)
void rnn_kernel(const float* __restrict__ last_pose,
                const float* __restrict__ context,
                const int*   __restrict__ d_nf,
                const float* __restrict__ b_in,
                const float* __restrict__ b_ih,
                const float* __restrict__ b_hh,
                const float* __restrict__ W_out,
                const float* __restrict__ b_out,
                float*       __restrict__ out)
{
    extern __shared__ float sm[];
    float* s_cb   = sm;                     // [256][28]  c_base = Wc@ctx + b_in
    float* s_x    = s_cb  + NHID * BT;      // [256][28]  x (temp: raw ctx at init)
    float* s_h0   = s_x   + NHID * BT;      // [256][28]  h ping
    float* s_h1   = s_h0  + NHID * BT;      // [256][28]  h pong
    float* s_pose = s_h1  + NHID * BT;      // [16][28]   pose (13 used)
    float* s_raw  = s_pose + 16 * BT;       // [16][28]   pre-norm pose

    const int tid  = threadIdx.x;
    const int j    = tid & (NHID - 1);      // hidden unit owned by this thread
    const int half = tid >> 8;              // 0: rows 0..15 (4 q), 1: rows 16..27 (3 q)
    const int r0   = half * 16;
    const int nr   = half ? 12 : 16;
    const int row0 = blockIdx.x * BT;
    const int nf   = d_nf[0];

    // --- init: raw ctx -> s_x (transposed), h=0; pose -> s_pose ---
    for (int rr = 0; rr < nr; rr++) {
        int r = r0 + rr;
        int grow = row0 + r; if (grow > NB - 1) grow = NB - 1;   // clamp pad rows
        s_x [j * BT + r] = context[(size_t)grow * NCTX + j];
        s_h0[j * BT + r] = 0.0f;
    }
    if (tid < NPOSE * BT) {
        int p = tid / BT, r = tid - p * BT;
        int grow = row0 + r; if (grow > NB - 1) grow = NB - 1;
        s_pose[p * BT + r] = last_pose[(size_t)grow * NPOSE + p];
    }
    const float binj = b_in[j];
    const float brz0 = b_ih[j]        + b_hh[j];          // fused r bias
    const float brz1 = b_ih[NHID + j] + b_hh[NHID + j];   // fused z bias
    const float bin_ = b_ih[2 * NHID + j];
    const float bhn  = b_hh[2 * NHID + j];
    __syncthreads();

    // --- precompute c_base = Wc @ ctx + b_in (hoisted out of the time loop) ---
    {
        float2 cb[8];
        if (half == 0) {
            #pragma unroll
            for (int p = 0; p < 8; p++) cb[p] = make_float2(binj, binj);
            gemm_in<4, 0>(g_Wctd, NCTX, s_x, j, cb);
            float2* co = reinterpret_cast<float2*>(s_cb + j * BT);
            #pragma unroll
            for (int p = 0; p < 8; p++) co[p] = cb[p];
        } else {
            #pragma unroll
            for (int p = 0; p < 6; p++) cb[p] = make_float2(binj, binj);
            gemm_in<3, 4>(g_Wctd, NCTX, s_x, j, cb);
            float2* co = reinterpret_cast<float2*>(s_cb + j * BT) + 8;
            #pragma unroll
            for (int p = 0; p < 6; p++) co[p] = cb[p];
        }
    }
    __syncthreads();

    for (int t = 0; t < nf; t++) {
        const float* hprev = (t & 1) ? s_h1 : s_h0;
        float*       hnext = (t & 1) ? s_h0 : s_h1;

        // ---- Phase A: x = relu(c_base + Wp @ pose), only 13 k-iterations ----
        if (half == 0) {
            float2 ax[8];
            const float2* cb = reinterpret_cast<const float2*>(s_cb + j * BT);
            #pragma unroll
            for (int p = 0; p < 8; p++) ax[p] = cb[p];
            gemm_in<4, 0>(g_Wptd, NPOSE, s_pose, j, ax);
            float2* xo = reinterpret_cast<float2*>(s_x + j * BT);
            #pragma unroll
            for (int p = 0; p < 8; p++)
                xo[p] = make_float2(fmaxf(ax[p].x, 0.0f), fmaxf(ax[p].y, 0.0f));
        } else {
            float2 ax[6];
            const float2* cb = reinterpret_cast<const float2*>(s_cb + j * BT) + 8;
            #pragma unroll
            for (int p = 0; p < 6; p++) ax[p] = cb[p];
            gemm_in<3, 4>(g_Wptd, NPOSE, s_pose, j, ax);
            float2* xo = reinterpret_cast<float2*>(s_x + j * BT) + 8;
            #pragma unroll
            for (int p = 0; p < 6; p++)
                xo[p] = make_float2(fmaxf(ax[p].x, 0.0f), fmaxf(ax[p].y, 0.0f));
        }
        __syncthreads();

        // ---- Phase B + C: gate GEMMs + GRU pointwise ----
        if (half == 0) gru_step<4, 0>(s_x, hprev, hnext, j, brz0, brz1, bin_, bhn);
        else           gru_step<3, 4>(s_x, hprev, hnext, j, brz0, brz1, bin_, bhn);
        __syncthreads();

        // ---- Phase D1: pose delta = h_new @ W_out^T + b_out (364 units) ----
        if (tid < NPOSE * BT) {
            int p = tid / BT, r = tid - p * BT;
            const float4* wo = reinterpret_cast<const float4*>(W_out + p * NHID);
            float acc = b_out[p];
            #pragma unroll 4
            for (int k4 = 0; k4 < NHID / 4; k4++) {
                float4 w4 = wo[k4];
                int kb = k4 * 4;
                acc = fmaf(hnext[(kb    ) * BT + r], w4.x, acc);
                acc = fmaf(hnext[(kb + 1) * BT + r], w4.y, acc);
                acc = fmaf(hnext[(kb + 2) * BT + r], w4.z, acc);
                acc = fmaf(hnext[(kb + 3) * BT + r], w4.w, acc);
            }
            s_raw[tid] = s_pose[tid] + acc;
        }
        __syncthreads();

        // ---- Phase D2: quaternion normalize + commit pose + store output ----
        if (tid < NPOSE * BT) {
            int p = tid / BT, r = tid - p * BT;
            float v = s_raw[tid];
            if (p >= 3 && p <= 6) {
                float q3 = s_raw[3 * BT + r], q4 = s_raw[4 * BT + r];
                float q5 = s_raw[5 * BT + r], q6 = s_raw[6 * BT + r];
                float nrm = fmaxf(sqrtf(q3*q3 + q4*q4 + q5*q5 + q6*q6), 1e-12f);
                v = v / nrm;
            }
            s_pose[tid] = v;
            int grow = row0 + r;
            if (grow < NB)
                out[((size_t)grow * nf + t) * NPOSE + p] = v;
        }
        __syncthreads();
    }
}

extern "C" void kernel_launch(void* const* d_in, const int* in_sizes, int n_in,
                              void* d_out, int out_size) {
    const float* last_pose = (const float*)d_in[0];
    const float* context   = (const float*)d_in[1];
    const int*   num_fut   = (const int*)  d_in[2];
    const float* W_in      = (const float*)d_in[3];
    const float* b_in      = (const float*)d_in[4];
    const float* W_ih      = (const float*)d_in[5];
    const float* b_ih      = (const float*)d_in[6];
    const float* W_hh      = (const float*)d_in[7];
    const float* b_hh      = (const float*)d_in[8];
    const float* W_out     = (const float*)d_in[9];
    const float* b_out     = (const float*)d_in[10];
    float* out = (float*)d_out;

    // packed weight transposes (L2-resident, deterministic each call)
    prep_kernel<<<(NHID * NHID + 255) / 256, 256>>>(W_in, W_ih, W_hh);

    const int smem_bytes = (4 * NHID * BT + 2 * 16 * BT) * (int)sizeof(float);
    cudaFuncSetAttribute(rnn_kernel,
                         cudaFuncAttributeMaxDynamicSharedMemorySize, smem_bytes);

    const int grid = (NB + BT - 1) / BT;   // 147 CTAs -> one wave
    rnn_kernel<<<grid, NTHR, smem_bytes>>>(last_pose, context, num_fut,
                                           b_in, b_ih, b_hh, W_out, b_out, out);
}

// round 7
// speedup vs baseline: 1.5454x; 1.0330x over previous
#include <cuda_runtime.h>

#define NB    4096
#define NPOSE 13
#define NHID  256
#define NIN   269
#define NCTX  256
#define BT    28      // batch rows per CTA
#define NTHR  512     // two halves: half 0 -> rows 0..15, half 1 -> rows 16..27

// Input-layer weights stay duplicated (tiny: 13 + one-time-256 k iterations).
__device__ float2 g_Wptd[NPOSE * NHID];          // W_in pose part: [k][j] -> (w,w)
__device__ float2 g_Wctd[NCTX  * NHID];          // W_in ctx  part: [k][j] -> (w,w)
// Gate weights PACKED, non-duplicated: 2 LDGs per k per thread.
__device__ float4 g_W4[NHID * NHID];             // [k][j] -> (w_ir, w_iz, w_in, w_hr)
__device__ float2 g_W2[NHID * NHID];             // [k][j] -> (w_hz, w_hn)

// Packed dual-fp32 FMA (Blackwell f32x2 pipe; only reachable via PTX).
__device__ __forceinline__ float2 ffma2(float2 a, float2 b, float2 c) {
    float2 d;
    asm("fma.rn.f32x2 %0, %1, %2, %3;"
        : "=l"(*reinterpret_cast<unsigned long long*>(&d))
        : "l"(*reinterpret_cast<unsigned long long*>(&a)),
          "l"(*reinterpret_cast<unsigned long long*>(&b)),
          "l"(*reinterpret_cast<unsigned long long*>(&c)));
    return d;
}

__device__ __forceinline__ float sigm(float a) {
    return 1.0f / (1.0f + __expf(-a));
}
__device__ __forceinline__ float tanh_acc(float a) {
    float e = __expf(-2.0f * fabsf(a));      // e in (0,1], overflow-safe
    float t = (1.0f - e) / (1.0f + e);
    return copysignf(t, a);
}

__global__ void prep_kernel(const float* __restrict__ W_in,
                            const float* __restrict__ W_ih,
                            const float* __restrict__ W_hh) {
    int i = blockIdx.x * blockDim.x + threadIdx.x;
    if (i < NPOSE * NHID) {
        int k = i / NHID, j = i % NHID;
        float w = W_in[j * NIN + k];
        g_Wptd[i] = make_float2(w, w);
    }
    if (i < NCTX * NHID) {
        int k = i / NHID, j = i % NHID;
        float w = W_in[j * NIN + NPOSE + k];
        g_Wctd[i] = make_float2(w, w);
    }
    if (i < NHID * NHID) {
        int k = i / NHID, j = i % NHID;
        g_W4[i] = make_float4(W_ih[(size_t)(0 * NHID + j) * NHID + k],
                              W_ih[(size_t)(1 * NHID + j) * NHID + k],
                              W_ih[(size_t)(2 * NHID + j) * NHID + k],
                              W_hh[(size_t)(0 * NHID + j) * NHID + k]);
        g_W2[i] = make_float2(W_hh[(size_t)(1 * NHID + j) * NHID + k],
                              W_hh[(size_t)(2 * NHID + j) * NHID + k]);
    }
}

// Dense input GEMM column for unit j over this half's rows (duplicated weights).
template<int NQH, int QOFF>
__device__ __forceinline__ void gemm_in(const float2* __restrict__ Wd, int nk,
                                        const float* __restrict__ src, int j,
                                        float2* ax)
{
    #pragma unroll 4
    for (int k = 0; k < nk; k++) {
        float2 w2 = Wd[k * NHID + j];
        const float4* pr = reinterpret_cast<const float4*>(src + k * BT) + QOFF;
        #pragma unroll
        for (int q = 0; q < NQH; q++) {
            float4 v = pr[q];
            ax[2*q]   = ffma2(make_float2(v.x, v.y), w2, ax[2*q]);
            ax[2*q+1] = ffma2(make_float2(v.z, v.w), w2, ax[2*q+1]);
        }
    }
}

// Phase B (six gate GEMM columns) + Phase C (GRU pointwise), unit j, this half's rows.
// Weight stream is software-pipelined one k ahead so each LDG has a full loop
// body of FMA issue to hide its L1-miss/L2 latency behind.
template<int NQH, int QOFF>
__device__ __forceinline__ void gru_step(const float* __restrict__ s_x,
                                         const float* __restrict__ hprev,
                                         float*       __restrict__ hnext,
                                         int j,
                                         float brz0, float brz1,
                                         float bin_, float bhn)
{
    constexpr int NP = 2 * NQH;
    float2 ar[NP], az[NP], ani[NP], anh[NP];
    #pragma unroll
    for (int p = 0; p < NP; p++) {
        ar[p] = make_float2(0.f, 0.f);
        az[p] = ar[p]; ani[p] = ar[p]; anh[p] = ar[p];
    }

    const float4* __restrict__ p4 = g_W4 + j;
    const float2* __restrict__ p2 = g_W2 + j;
    float4 wa = p4[0];                     // k = 0 preload
    float2 wb = p2[0];

    #pragma unroll 2
    for (int k = 0; k < NHID; k++) {
        // prefetch k+1 (clamped; redundant last load is an L1 hit)
        int kn = (k < NHID - 1) ? (k + 1) : k;
        float4 wa_n = p4[(size_t)kn * NHID];
        float2 wb_n = p2[(size_t)kn * NHID];

        // duplicate to lane pairs on the alu pipe (fma pipe untouched)
        float2 wir = make_float2(wa.x, wa.x);
        float2 wiz = make_float2(wa.y, wa.y);
        float2 win = make_float2(wa.z, wa.z);
        float2 whr = make_float2(wa.w, wa.w);
        float2 whz = make_float2(wb.x, wb.x);
        float2 whn = make_float2(wb.y, wb.y);

        const float4* xr = reinterpret_cast<const float4*>(s_x   + k * BT) + QOFF;
        const float4* hr = reinterpret_cast<const float4*>(hprev + k * BT) + QOFF;
        #pragma unroll
        for (int q = 0; q < NQH; q++) {
            float4 xv = xr[q];                 // LDS.128 broadcast (conflict-free)
            float4 hv = hr[q];
            float2 x0 = make_float2(xv.x, xv.y), x1 = make_float2(xv.z, xv.w);
            float2 h0 = make_float2(hv.x, hv.y), h1 = make_float2(hv.z, hv.w);
            ar [2*q]   = ffma2(x0, wir, ar [2*q]);
            ar [2*q]   = ffma2(h0, whr, ar [2*q]);
            ar [2*q+1] = ffma2(x1, wir, ar [2*q+1]);
            ar [2*q+1] = ffma2(h1, whr, ar [2*q+1]);
            az [2*q]   = ffma2(x0, wiz, az [2*q]);
            az [2*q]   = ffma2(h0, whz, az [2*q]);
            az [2*q+1] = ffma2(x1, wiz, az [2*q+1]);
            az [2*q+1] = ffma2(h1, whz, az [2*q+1]);
            ani[2*q]   = ffma2(x0, win, ani[2*q]);
            ani[2*q+1] = ffma2(x1, win, ani[2*q+1]);
            anh[2*q]   = ffma2(h0, whn, anh[2*q]);
            anh[2*q+1] = ffma2(h1, whn, anh[2*q+1]);
        }
        wa = wa_n;
        wb = wb_n;
    }

    // GRU pointwise, registers only
    const float2* hop = reinterpret_cast<const float2*>(hprev + j * BT) + QOFF * 2;
    float2*       hnp = reinterpret_cast<float2*>(hnext + j * BT) + QOFF * 2;
    #pragma unroll
    for (int p = 0; p < NP; p++) {
        float2 ho = hop[p];
        float rr = sigm(ar[p].x + brz0);
        float zz = sigm(az[p].x + brz1);
        float nn = tanh_acc(ani[p].x + bin_ + rr * (anh[p].x + bhn));
        float hx = (1.0f - zz) * nn + zz * ho.x;
        rr = sigm(ar[p].y + brz0);
        zz = sigm(az[p].y + brz1);
        nn = tanh_acc(ani[p].y + bin_ + rr * (anh[p].y + bhn));
        float hy = (1.0f - zz) * nn + zz * ho.y;
        hnp[p] = make_float2(hx, hy);
    }
}

__global__ __launch_bounds__(NTHR, 1)
void rnn_kernel(const float* __restrict__ last_pose,
                const float* __restrict__ context,
                const int*   __restrict__ d_nf,
                const float* __restrict__ b_in,
                const float* __restrict__ b_ih,
                const float* __restrict__ b_hh,
                const float* __restrict__ W_out,
                const float* __restrict__ b_out,
                float*       __restrict__ out)
{
    extern __shared__ float sm[];
    float* s_cb   = sm;                     // [256][28]  c_base = Wc@ctx + b_in
    float* s_x    = s_cb  + NHID * BT;      // [256][28]  x (temp: raw ctx at init)
    float* s_h0   = s_x   + NHID * BT;      // [256][28]  h ping
    float* s_h1   = s_h0  + NHID * BT;      // [256][28]  h pong
    float* s_pose = s_h1  + NHID * BT;      // [16][28]   pose (13 used)
    float* s_raw  = s_pose + 16 * BT;       // [16][28]   pre-norm pose

    const int tid  = threadIdx.x;
    const int j    = tid & (NHID - 1);      // hidden unit owned by this thread
    const int half = tid >> 8;              // 0: rows 0..15 (4 q), 1: rows 16..27 (3 q)
    const int r0   = half * 16;
    const int nr   = half ? 12 : 16;
    const int row0 = blockIdx.x * BT;
    const int nf   = d_nf[0];

    // --- init: raw ctx -> s_x (transposed), h=0; pose -> s_pose ---
    for (int rr = 0; rr < nr; rr++) {
        int r = r0 + rr;
        int grow = row0 + r; if (grow > NB - 1) grow = NB - 1;   // clamp pad rows
        s_x [j * BT + r] = context[(size_t)grow * NCTX + j];
        s_h0[j * BT + r] = 0.0f;
    }
    if (tid < NPOSE * BT) {
        int p = tid / BT, r = tid - p * BT;
        int grow = row0 + r; if (grow > NB - 1) grow = NB - 1;
        s_pose[p * BT + r] = last_pose[(size_t)grow * NPOSE + p];
    }
    const float binj = b_in[j];
    const float brz0 = b_ih[j]        + b_hh[j];          // fused r bias
    const float brz1 = b_ih[NHID + j] + b_hh[NHID + j];   // fused z bias
    const float bin_ = b_ih[2 * NHID + j];
    const float bhn  = b_hh[2 * NHID + j];
    __syncthreads();

    // --- precompute c_base = Wc @ ctx + b_in (hoisted out of the time loop) ---
    {
        float2 cb[8];
        if (half == 0) {
            #pragma unroll
            for (int p = 0; p < 8; p++) cb[p] = make_float2(binj, binj);
            gemm_in<4, 0>(g_Wctd, NCTX, s_x, j, cb);
            float2* co = reinterpret_cast<float2*>(s_cb + j * BT);
            #pragma unroll
            for (int p = 0; p < 8; p++) co[p] = cb[p];
        } else {
            #pragma unroll
            for (int p = 0; p < 6; p++) cb[p] = make_float2(binj, binj);
            gemm_in<3, 4>(g_Wctd, NCTX, s_x, j, cb);
            float2* co = reinterpret_cast<float2*>(s_cb + j * BT) + 8;
            #pragma unroll
            for (int p = 0; p < 6; p++) co[p] = cb[p];
        }
    }
    __syncthreads();

    for (int t = 0; t < nf; t++) {
        const float* hprev = (t & 1) ? s_h1 : s_h0;
        float*       hnext = (t & 1) ? s_h0 : s_h1;

        // ---- Phase A: x = relu(c_base + Wp @ pose), only 13 k-iterations ----
        if (half == 0) {
            float2 ax[8];
            const float2* cb = reinterpret_cast<const float2*>(s_cb + j * BT);
            #pragma unroll
            for (int p = 0; p < 8; p++) ax[p] = cb[p];
            gemm_in<4, 0>(g_Wptd, NPOSE, s_pose, j, ax);
            float2* xo = reinterpret_cast<float2*>(s_x + j * BT);
            #pragma unroll
            for (int p = 0; p < 8; p++)
                xo[p] = make_float2(fmaxf(ax[p].x, 0.0f), fmaxf(ax[p].y, 0.0f));
        } else {
            float2 ax[6];
            const float2* cb = reinterpret_cast<const float2*>(s_cb + j * BT) + 8;
            #pragma unroll
            for (int p = 0; p < 6; p++) ax[p] = cb[p];
            gemm_in<3, 4>(g_Wptd, NPOSE, s_pose, j, ax);
            float2* xo = reinterpret_cast<float2*>(s_x + j * BT) + 8;
            #pragma unroll
            for (int p = 0; p < 6; p++)
                xo[p] = make_float2(fmaxf(ax[p].x, 0.0f), fmaxf(ax[p].y, 0.0f));
        }
        __syncthreads();

        // ---- Phase B + C: gate GEMMs + GRU pointwise ----
        if (half == 0) gru_step<4, 0>(s_x, hprev, hnext, j, brz0, brz1, bin_, bhn);
        else           gru_step<3, 4>(s_x, hprev, hnext, j, brz0, brz1, bin_, bhn);
        __syncthreads();

        // ---- Phase D1: pose delta = h_new @ W_out^T + b_out (364 units) ----
        // 4 independent partials break the serial fmaf RAW chain.
        if (tid < NPOSE * BT) {
            int p = tid / BT, r = tid - p * BT;
            const float4* wo = reinterpret_cast<const float4*>(W_out + p * NHID);
            float a0 = b_out[p], a1 = 0.f, a2 = 0.f, a3 = 0.f;
            #pragma unroll 4
            for (int k4 = 0; k4 < NHID / 4; k4++) {
                float4 w4 = wo[k4];
                int kb = k4 * 4;
                a0 = fmaf(hnext[(kb    ) * BT + r], w4.x, a0);
                a1 = fmaf(hnext[(kb + 1) * BT + r], w4.y, a1);
                a2 = fmaf(hnext[(kb + 2) * BT + r], w4.z, a2);
                a3 = fmaf(hnext[(kb + 3) * BT + r], w4.w, a3);
            }
            s_raw[tid] = s_pose[tid] + ((a0 + a1) + (a2 + a3));
        }
        __syncthreads();

        // ---- Phase D2: quaternion normalize + commit pose + store output ----
        if (tid < NPOSE * BT) {
            int p = tid / BT, r = tid - p * BT;
            float v = s_raw[tid];
            if (p >= 3 && p <= 6) {
                float q3 = s_raw[3 * BT + r], q4 = s_raw[4 * BT + r];
                float q5 = s_raw[5 * BT + r], q6 = s_raw[6 * BT + r];
                float nrm = fmaxf(sqrtf(q3*q3 + q4*q4 + q5*q5 + q6*q6), 1e-12f);
                v = v / nrm;
            }
            s_pose[tid] = v;
            int grow = row0 + r;
            if (grow < NB)
                out[((size_t)grow * nf + t) * NPOSE + p] = v;
        }
        __syncthreads();
    }
}

extern "C" void kernel_launch(void* const* d_in, const int* in_sizes, int n_in,
                              void* d_out, int out_size) {
    const float* last_pose = (const float*)d_in[0];
    const float* context   = (const float*)d_in[1];
    const int*   num_fut   = (const int*)  d_in[2];
    const float* W_in      = (const float*)d_in[3];
    const float* b_in      = (const float*)d_in[4];
    const float* W_ih      = (const float*)d_in[5];
    const float* b_ih      = (const float*)d_in[6];
    const float* W_hh      = (const float*)d_in[7];
    const float* b_hh      = (const float*)d_in[8];
    const float* W_out     = (const float*)d_in[9];
    const float* b_out     = (const float*)d_in[10];
    float* out = (float*)d_out;

    // packed weight transposes (L2-resident, deterministic each call)
    prep_kernel<<<(NHID * NHID + 255) / 256, 256>>>(W_in, W_ih, W_hh);

    const int smem_bytes = (4 * NHID * BT + 2 * 16 * BT) * (int)sizeof(float);
    cudaFuncSetAttribute(rnn_kernel,
                         cudaFuncAttributeMaxDynamicSharedMemorySize, smem_bytes);

    const int grid = (NB + BT - 1) / BT;   // 147 CTAs -> one wave
    rnn_kernel<<<grid, NTHR, smem_bytes>>>(last_pose, context, num_fut,
                                           b_in, b_ih, b_hh, W_out, b_out, out);
}